// round 1
// baseline (speedup 1.0000x reference)
#include <cuda_runtime.h>

// ---------------- problem constants ----------------
#define BB   2
#define SEQ  2048
#define DIM  1024
#define NH   16
#define HD   64
#define BN   (BB*SEQ)       // 4096 rows
#define QKVC (3*HD)         // 192 per head (k,q,v order)
#define NQKV (NH*QKVC)      // 3072

// ---------------- scratch (device globals; no allocation allowed) ----------------
__device__ float g_Wpk[DIM * NQKV];   // repacked QKV weight [1024][3072]
__device__ float g_bpk[NQKV];         // repacked QKV bias  [3072]
__device__ float g_qkv[BN * NQKV];    // qkv activations    [4096][3072]
__device__ float g_sa [BN * DIM];     // attention output   [4096][1024]

// ---------------- repack Wqkv [H,D,192] -> [D, H*192] ----------------
__global__ void repack_kernel(const float* __restrict__ Wqkv,
                              const float* __restrict__ bqkv)
{
    int idx = blockIdx.x * blockDim.x + threadIdx.x;
    if (idx < DIM * NQKV) {
        int d = idx / NQKV;
        int c = idx % NQKV;
        int h = c / QKVC;
        int j = c % QKVC;
        g_Wpk[idx] = Wqkv[(h * DIM + d) * QKVC + j];
    }
    if (idx < NQKV) g_bpk[idx] = bqkv[idx];   // bqkv is [H,192] contiguous == c order
}

// ---------------- SGEMM 128x128x8, 256 threads, 8x8 microtile ----------------
// C[M,N] = A[M,K] @ B[K,N] + bias[N]   (all row-major, M%128==0, N%128==0, K%8==0)
__global__ __launch_bounds__(256)
void sgemm_kernel(const float* __restrict__ A, const float* __restrict__ B,
                  const float* __restrict__ bias, float* __restrict__ C,
                  int M, int N, int K)
{
    __shared__ float As[8][128];   // transposed A tile: As[k][m]
    __shared__ float Bs[8][128];

    const int tid = threadIdx.x;
    const int tx  = tid & 15;          // 0..15  -> 8 cols each
    const int ty  = tid >> 4;          // 0..15  -> 8 rows each
    const int m0  = blockIdx.y * 128;
    const int n0  = blockIdx.x * 128;

    const int arow = tid >> 1;          // 0..127
    const int acol = (tid & 1) * 4;     // 0 or 4
    const int brow = tid >> 5;          // 0..7
    const int bcol = (tid & 31) * 4;    // 0..124

    const float* Ab = A + (size_t)m0 * K;
    const float* Bb = B + n0;

    float acc[8][8];
#pragma unroll
    for (int i = 0; i < 8; i++)
#pragma unroll
        for (int j = 0; j < 8; j++) acc[i][j] = 0.f;

    for (int k0 = 0; k0 < K; k0 += 8) {
        float4 a4 = *(const float4*)(Ab + (size_t)arow * K + k0 + acol);
        As[acol + 0][arow] = a4.x;
        As[acol + 1][arow] = a4.y;
        As[acol + 2][arow] = a4.z;
        As[acol + 3][arow] = a4.w;
        float4 b4 = *(const float4*)(Bb + (size_t)(k0 + brow) * N + bcol);
        *(float4*)&Bs[brow][bcol] = b4;
        __syncthreads();

#pragma unroll
        for (int kk = 0; kk < 8; kk++) {
            float4 aA = *(const float4*)&As[kk][ty * 8];
            float4 aB = *(const float4*)&As[kk][ty * 8 + 4];
            float4 bA = *(const float4*)&Bs[kk][tx * 8];
            float4 bB = *(const float4*)&Bs[kk][tx * 8 + 4];
            float a[8] = {aA.x, aA.y, aA.z, aA.w, aB.x, aB.y, aB.z, aB.w};
            float b[8] = {bA.x, bA.y, bA.z, bA.w, bB.x, bB.y, bB.z, bB.w};
#pragma unroll
            for (int i = 0; i < 8; i++)
#pragma unroll
                for (int j = 0; j < 8; j++) acc[i][j] = fmaf(a[i], b[j], acc[i][j]);
        }
        __syncthreads();
    }

#pragma unroll
    for (int i = 0; i < 8; i++) {
        int m = m0 + ty * 8 + i;
#pragma unroll
        for (int j = 0; j < 8; j += 4) {
            int n = n0 + tx * 8 + j;
            float4 r;
            r.x = acc[i][j + 0] + bias[n + 0];
            r.y = acc[i][j + 1] + bias[n + 1];
            r.z = acc[i][j + 2] + bias[n + 2];
            r.w = acc[i][j + 3] + bias[n + 3];
            *(float4*)&C[(size_t)m * N + n] = r;
        }
    }
}

// ---------------- flash attention, 64-query tile, 256 threads ----------------
// grid: (SEQ/64, NH, BB).  qkv chunk order per head: [k(64) | q(64) | v(64)].
#define TS    64
#define LDSA  65          // padded smem stride (banks)
#define ATTN_SMEM (4 * TS * LDSA * sizeof(float))

__global__ __launch_bounds__(256)
void attn_kernel(const float* __restrict__ qkv, float* __restrict__ sa)
{
    extern __shared__ float sm[];
    float* Qs = sm;
    float* Ks = Qs + TS * LDSA;
    float* Vs = Ks + TS * LDSA;
    float* Ps = Vs + TS * LDSA;

    const int qt  = blockIdx.x;
    const int h   = blockIdx.y;
    const int b   = blockIdx.z;
    const int tid = threadIdx.x;
    const int tx  = tid & 15;     // key/dim cols: 4 each
    const int ty  = tid >> 4;     // query rows: 4 each

    const int   bn0  = b * SEQ;
    const int   colK = h * QKVC;
    const int   colQ = colK + HD;
    const int   colV = colK + 2 * HD;
    const float scale = 0.125f;   // 1/sqrt(64)

    // load Q tile
    for (int idx = tid; idx < TS * HD; idx += 256) {
        int r = idx / HD, c = idx % HD;
        Qs[r * LDSA + c] = qkv[(size_t)(bn0 + qt * TS + r) * NQKV + colQ + c];
    }

    float acc[4][4];
    float m_i[4], l_i[4];
#pragma unroll
    for (int i = 0; i < 4; i++) {
        m_i[i] = -1e30f; l_i[i] = 0.f;
#pragma unroll
        for (int j = 0; j < 4; j++) acc[i][j] = 0.f;
    }

    for (int kt = 0; kt <= qt; kt++) {
        __syncthreads();  // previous PV reads done (also orders Q load on first iter)
        for (int idx = tid; idx < TS * HD; idx += 256) {
            int r = idx / HD, c = idx % HD;
            size_t base = (size_t)(bn0 + kt * TS + r) * NQKV;
            Ks[r * LDSA + c] = qkv[base + colK + c];
            Vs[r * LDSA + c] = qkv[base + colV + c];
        }
        __syncthreads();

        // S = Q @ K^T  (4x4 microtile per thread)
        float s[4][4];
#pragma unroll
        for (int i = 0; i < 4; i++)
#pragma unroll
            for (int j = 0; j < 4; j++) s[i][j] = 0.f;
#pragma unroll 8
        for (int kk = 0; kk < HD; kk++) {
            float qv[4], kv[4];
#pragma unroll
            for (int i = 0; i < 4; i++) qv[i] = Qs[(ty * 4 + i) * LDSA + kk];
#pragma unroll
            for (int j = 0; j < 4; j++) kv[j] = Ks[(tx * 4 + j) * LDSA + kk];
#pragma unroll
            for (int i = 0; i < 4; i++)
#pragma unroll
                for (int j = 0; j < 4; j++) s[i][j] = fmaf(qv[i], kv[j], s[i][j]);
        }

        const bool diag = (kt == qt);
#pragma unroll
        for (int i = 0; i < 4; i++)
#pragma unroll
            for (int j = 0; j < 4; j++) {
                s[i][j] *= scale;
                if (diag && (tx * 4 + j) > (ty * 4 + i)) s[i][j] = -1e30f;
            }

        // online softmax per query row (row owned by 16 consecutive lanes)
        float alpha[4];
#pragma unroll
        for (int i = 0; i < 4; i++) {
            float mx = s[i][0];
#pragma unroll
            for (int j = 1; j < 4; j++) mx = fmaxf(mx, s[i][j]);
#pragma unroll
            for (int off = 8; off >= 1; off >>= 1)
                mx = fmaxf(mx, __shfl_xor_sync(0xffffffffu, mx, off));
            float mnew = fmaxf(m_i[i], mx);
            alpha[i] = __expf(m_i[i] - mnew);
            float lsum = 0.f;
#pragma unroll
            for (int j = 0; j < 4; j++) {
                float p = __expf(s[i][j] - mnew);
                Ps[(ty * 4 + i) * LDSA + (tx * 4 + j)] = p;
                lsum += p;
            }
#pragma unroll
            for (int off = 8; off >= 1; off >>= 1)
                lsum += __shfl_xor_sync(0xffffffffu, lsum, off);
            l_i[i] = l_i[i] * alpha[i] + lsum;
            m_i[i] = mnew;
        }
#pragma unroll
        for (int i = 0; i < 4; i++)
#pragma unroll
            for (int j = 0; j < 4; j++) acc[i][j] *= alpha[i];
        __syncthreads();  // Ps complete

        // O += P @ V
#pragma unroll 8
        for (int k = 0; k < TS; k++) {
            float pv[4], vv[4];
#pragma unroll
            for (int i = 0; i < 4; i++) pv[i] = Ps[(ty * 4 + i) * LDSA + k];
#pragma unroll
            for (int j = 0; j < 4; j++) vv[j] = Vs[k * LDSA + (tx * 4 + j)];
#pragma unroll
            for (int i = 0; i < 4; i++)
#pragma unroll
                for (int j = 0; j < 4; j++) acc[i][j] = fmaf(pv[i], vv[j], acc[i][j]);
        }
    }

    // write concat-head output: sa[b, n, h*64 + d]
#pragma unroll
    for (int i = 0; i < 4; i++) {
        float inv = 1.f / l_i[i];
        int n = bn0 + qt * TS + ty * 4 + i;
#pragma unroll
        for (int j = 0; j < 4; j++)
            sa[(size_t)n * DIM + h * HD + tx * 4 + j] = acc[i][j] * inv;
    }
}

// ---------------- launch ----------------
extern "C" void kernel_launch(void* const* d_in, const int* in_sizes, int n_in,
                              void* d_out, int out_size)
{
    const float* x    = (const float*)d_in[0];
    const float* Wqkv = (const float*)d_in[1];
    const float* bqkv = (const float*)d_in[2];
    const float* Wo   = (const float*)d_in[3];
    const float* bo   = (const float*)d_in[4];
    float* out = (float*)d_out;

    float *Wpk, *bpk, *qkv, *sa;
    cudaGetSymbolAddress((void**)&Wpk, g_Wpk);
    cudaGetSymbolAddress((void**)&bpk, g_bpk);
    cudaGetSymbolAddress((void**)&qkv, g_qkv);
    cudaGetSymbolAddress((void**)&sa,  g_sa);

    cudaFuncSetAttribute(attn_kernel, cudaFuncAttributeMaxDynamicSharedMemorySize,
                         (int)ATTN_SMEM);

    // 1. repack weights + bias
    repack_kernel<<<(DIM * NQKV + 255) / 256, 256>>>(Wqkv, bqkv);

    // 2. QKV projection: [4096,1024] @ [1024,3072] + bias
    sgemm_kernel<<<dim3(NQKV / 128, BN / 128), 256>>>(x, Wpk, bpk, qkv, BN, NQKV, DIM);

    // 3. flash attention per (qtile, head, batch)
    attn_kernel<<<dim3(SEQ / TS, NH, BB), 256, ATTN_SMEM>>>(qkv, sa);

    // 4. output projection: [4096,1024] @ [1024,1024] + bias
    sgemm_kernel<<<dim3(DIM / 128, BN / 128), 256>>>(sa, Wo, bo, out, BN, DIM, DIM);
}